// round 4
// baseline (speedup 1.0000x reference)
#include <cuda_runtime.h>
#include <math.h>

// Problem constants
#define Bsz    64
#define Ssz    512
#define Hsz    256
#define Dsz    207
#define DINsz  414

// Partition: 4 batch-groups x 32 hidden-groups = 128 blocks
#define GRID    128
#define THREADS 256
#define NB      16        // batch per block
#define NI      8         // hidden units per block
#define NROWB   24        // 3*NI gate rows
#define XS_STR  416       // 414 padded to /4 (broadcast loads: conflicts irrelevant)
#define KBC     52        // per-warp K chunk for phase B (8*52 = 416)
#define SC_STR  33        // scratch row pad (conflict-free reduce)

// Persistent global state (device globals: no runtime allocation)
__device__ float    g_h[Bsz * Hsz];
__device__ float    g_xh[Bsz * Dsz];
__device__ unsigned g_flags[GRID * 8];   // one flag per block, 32B apart

// Split-phase group barrier (32-block batch-group scope).
__device__ __forceinline__ void bar_release(unsigned target) {
    __syncthreads();
    if (threadIdx.x == 0) {
        asm volatile("st.release.gpu.u32 [%0], %1;"
                     :: "l"(g_flags + blockIdx.x * 8), "r"(target) : "memory");
    }
}
__device__ __forceinline__ void bar_wait(int gbase, unsigned target) {
    if (threadIdx.x < 32) {
        const unsigned* p = g_flags + (gbase + threadIdx.x) * 8;
        unsigned v;
        do {
            asm volatile("ld.acquire.gpu.u32 %0, [%1];" : "=r"(v) : "l"(p) : "memory");
        } while ((int)(v - target) < 0);
    }
    __syncthreads();
}

__global__ void __launch_bounds__(THREADS, 1)
rnn_imputer_kernel(const float* __restrict__ x, const float* __restrict__ mask,
                   const float* __restrict__ Wih, const float* __restrict__ Whh,
                   const float* __restrict__ bih, const float* __restrict__ bhh,
                   const float* __restrict__ Wro, const float* __restrict__ bro,
                   float* __restrict__ out)
{
    extern __shared__ float sm[];
    float* xs    = sm;                      // 16*416  x_in staging [x_p | mask]
    float* hs    = xs + NB * XS_STR;        // 16*256  h staging
    float* sc    = hs + NB * Hsz;           // 16*8*33 partial-sum scratch
    float* gi_s  = sc + NB * 8 * SC_STR;    // 16*24
    float* gh_s  = gi_s + NB * NROWB;       // 16*24
    float* bih_s = gh_s + NB * NROWB;       // 24
    float* bhh_s = bih_s + NROWB;           // 24
    float* bro_s = bhh_s + NROWB;           // 8

    const int tid = threadIdx.x, blk = blockIdx.x;
    const int bg = blk >> 5, ig = blk & 31;
    const int gbase = bg << 5;
    const int b0 = bg * NB;
    const int i0 = ig * NI;
    const int d0 = ig * 6 + (ig < 15 ? ig : 15);
    const int nd = (ig < 15) ? 7 : 6;

    const int lane = tid & 31, w = tid >> 5;

    // ---- weight fragments into REGISTERS (row = lane, K-chunk = warp) ----
    float wA[32];   // Whh rows 0..23 / Wro rows 24..24+nd, cols [w*32, w*32+32)
    float wB[KBC];  // Wih rows 0..23, cols [w*52, w*52+52)
    {
        const int row = lane;
        int ii = row / 3, g = row - ii * 3;
#pragma unroll
        for (int j = 0; j < 32; ++j) {
            float v = 0.f;
            int col = w * 32 + j;
            if (row < NROWB)              v = Whh[(g * Hsz + i0 + ii) * Hsz + col];
            else if (row - NROWB < nd)    v = Wro[(d0 + row - NROWB) * Hsz + col];
            wA[j] = v;
        }
#pragma unroll
        for (int j = 0; j < KBC; ++j) {
            float v = 0.f;
            int col = w * KBC + j;
            if (row < NROWB && col < DINsz)
                v = Wih[(g * Hsz + i0 + ii) * DINsz + col];
            wB[j] = v;
        }
    }

    // ---- biases + pads + h init + x[0] prefetch ----
    if (tid < NROWB) {
        int ii = tid / 3, g = tid - ii * 3;
        bih_s[tid] = bih[g * Hsz + i0 + ii];
        bhh_s[tid] = bhh[g * Hsz + i0 + ii];
    }
    if (tid < nd) bro_s[tid] = bro[d0 + tid];
    if (tid < NB * 2)   // zero xs[b][414..415]
        xs[(tid >> 1) * XS_STR + DINsz + (tid & 1)] = 0.f;
    for (int idx = tid; idx < NB * Dsz; idx += THREADS) {
        int b = idx / Dsz, k = idx - b * Dsz;
        size_t o = ((size_t)(b0 + b) * Ssz) * Dsz + k;
        xs[b * XS_STR + k] = x[o];
        xs[b * XS_STR + Dsz + k] = mask[o];
    }
    if (tid < NB * NI) {
        int b = tid >> 3, ii = tid & 7;
        g_h[(b0 + b) * Hsz + i0 + ii] = 0.f;
    }

    unsigned base = *(volatile unsigned*)(g_flags + blk * 8);
    unsigned cnt = 0;
    bar_release(base + (++cnt));
    bar_wait(gbase, base + cnt);     // init complete

    for (int t = 0; t < Ssz; ++t) {
        // ---- stage h_t ----
        for (int idx = tid; idx < NB * 64; idx += THREADS) {
            int b = idx >> 6, c = idx & 63;
            float4 v = __ldcg(reinterpret_cast<const float4*>(g_h + (b0 + b) * Hsz) + c);
            *(reinterpret_cast<float4*>(hs + b * Hsz) + c) = v;
        }
        __syncthreads();

        // ---- PHASE A: partials of [Whh; Wro] @ h (x broadcast, w in regs) ----
        for (int b = 0; b < NB; b += 2) {
            const float4* x0 = reinterpret_cast<const float4*>(hs + b * Hsz + w * 32);
            const float4* x1 = reinterpret_cast<const float4*>(hs + (b + 1) * Hsz + w * 32);
            float a0 = 0.f, a0b = 0.f, a1 = 0.f, a1b = 0.f;
#pragma unroll
            for (int jj = 0; jj < 8; jj += 2) {
                float4 v0 = x0[jj], u0 = x0[jj + 1];
                float4 v1 = x1[jj], u1 = x1[jj + 1];
                a0  = fmaf(wA[jj*4+0], v0.x, a0);  a0  = fmaf(wA[jj*4+1], v0.y, a0);
                a0  = fmaf(wA[jj*4+2], v0.z, a0);  a0  = fmaf(wA[jj*4+3], v0.w, a0);
                a0b = fmaf(wA[jj*4+4], u0.x, a0b); a0b = fmaf(wA[jj*4+5], u0.y, a0b);
                a0b = fmaf(wA[jj*4+6], u0.z, a0b); a0b = fmaf(wA[jj*4+7], u0.w, a0b);
                a1  = fmaf(wA[jj*4+0], v1.x, a1);  a1  = fmaf(wA[jj*4+1], v1.y, a1);
                a1  = fmaf(wA[jj*4+2], v1.z, a1);  a1  = fmaf(wA[jj*4+3], v1.w, a1);
                a1b = fmaf(wA[jj*4+4], u1.x, a1b); a1b = fmaf(wA[jj*4+5], u1.y, a1b);
                a1b = fmaf(wA[jj*4+6], u1.z, a1b); a1b = fmaf(wA[jj*4+7], u1.w, a1b);
            }
            sc[(b * 8 + w) * SC_STR + lane]       = a0 + a0b;
            sc[((b + 1) * 8 + w) * SC_STR + lane] = a1 + a1b;
        }
        __syncthreads();

        // ---- reduce A: gh rows -> gh_s, readout rows -> g_xh/out ----
#pragma unroll
        for (int h2 = 0; h2 < 2; ++h2) {
            int p = tid + h2 * 256;
            int b = p >> 5, row = p & 31;
            float s = 0.f;
#pragma unroll
            for (int ww = 0; ww < 8; ++ww) s += sc[(b * 8 + ww) * SC_STR + row];
            if (row < NROWB) {
                gh_s[b * NROWB + row] = s;
            } else if (row - NROWB < nd) {
                int dd = row - NROWB, gb = b0 + b;
                float v = s + bro_s[dd];
                g_xh[gb * Dsz + d0 + dd] = v;
                out[((size_t)gb * Ssz + t) * Dsz + d0 + dd] = v;
            }
        }
        if (t == Ssz - 1) break;          // last step: only readout needed
        bar_release(base + (++cnt));      // publish x_hat (syncthreads inside)
        bar_wait(gbase, base + cnt);      // peers' x_hat ready

        // ---- B0: patch unobserved entries with x_hat ----
        for (int idx = tid; idx < NB * Dsz; idx += THREADS) {
            int b = idx / Dsz, k = idx - b * Dsz;
            float mv = xs[b * XS_STR + Dsz + k];
            if (mv <= 0.5f)
                xs[b * XS_STR + k] = __ldcg(g_xh + (b0 + b) * Dsz + k);
        }
        __syncthreads();

        // ---- PHASE B: partials of Wih @ x_in ----
        for (int b = 0; b < NB; b += 2) {
            const float4* x0 = reinterpret_cast<const float4*>(xs + b * XS_STR + w * KBC);
            const float4* x1 = reinterpret_cast<const float4*>(xs + (b + 1) * XS_STR + w * KBC);
            float a0 = 0.f, a0b = 0.f, a1 = 0.f, a1b = 0.f;
#pragma unroll
            for (int jj = 0; jj < 13; ++jj) {
                float4 v0 = x0[jj];
                float4 v1 = x1[jj];
                if (jj & 1) {
                    a0b = fmaf(wB[jj*4+0], v0.x, a0b); a0b = fmaf(wB[jj*4+1], v0.y, a0b);
                    a0b = fmaf(wB[jj*4+2], v0.z, a0b); a0b = fmaf(wB[jj*4+3], v0.w, a0b);
                    a1b = fmaf(wB[jj*4+0], v1.x, a1b); a1b = fmaf(wB[jj*4+1], v1.y, a1b);
                    a1b = fmaf(wB[jj*4+2], v1.z, a1b); a1b = fmaf(wB[jj*4+3], v1.w, a1b);
                } else {
                    a0  = fmaf(wB[jj*4+0], v0.x, a0);  a0  = fmaf(wB[jj*4+1], v0.y, a0);
                    a0  = fmaf(wB[jj*4+2], v0.z, a0);  a0  = fmaf(wB[jj*4+3], v0.w, a0);
                    a1  = fmaf(wB[jj*4+0], v1.x, a1);  a1  = fmaf(wB[jj*4+1], v1.y, a1);
                    a1  = fmaf(wB[jj*4+2], v1.z, a1);  a1  = fmaf(wB[jj*4+3], v1.w, a1);
                }
            }
            sc[(b * 8 + w) * SC_STR + lane]       = a0 + a0b;
            sc[((b + 1) * 8 + w) * SC_STR + lane] = a1 + a1b;
        }
        __syncthreads();

        // ---- reduce B -> gi_s ----
#pragma unroll
        for (int h2 = 0; h2 < 2; ++h2) {
            int p = tid + h2 * 256;
            int b = p >> 5, row = p & 31;
            if (row < NROWB) {
                float s = 0.f;
#pragma unroll
                for (int ww = 0; ww < 8; ++ww) s += sc[(b * 8 + ww) * SC_STR + row];
                gi_s[b * NROWB + row] = s;
            }
        }
        __syncthreads();

        // ---- gates -> h_new ----
        if (tid < NB * NI) {
            int b = tid >> 3, ii = tid & 7;
            int r3 = ii * 3;
            float ir  = gi_s[b * NROWB + r3]     + bih_s[r3];
            float iz  = gi_s[b * NROWB + r3 + 1] + bih_s[r3 + 1];
            float inn = gi_s[b * NROWB + r3 + 2] + bih_s[r3 + 2];
            float hr  = gh_s[b * NROWB + r3]     + bhh_s[r3];
            float hz  = gh_s[b * NROWB + r3 + 1] + bhh_s[r3 + 1];
            float hn  = gh_s[b * NROWB + r3 + 2] + bhh_s[r3 + 2];
            float r = 1.f / (1.f + expf(-(ir + hr)));
            float z = 1.f / (1.f + expf(-(iz + hz)));
            float n = tanhf(inn + r * hn);
            float hold = hs[b * Hsz + i0 + ii];
            g_h[(b0 + b) * Hsz + i0 + ii] = (1.f - z) * n + z * hold;
        }
        bar_release(base + (++cnt));      // publish h_new (syncthreads inside)

        // ---- prefetch x[t+1], mask[t+1] (overlaps barrier B) ----
        for (int idx = tid; idx < NB * Dsz; idx += THREADS) {
            int b = idx / Dsz, k = idx - b * Dsz;
            size_t o = ((size_t)(b0 + b) * Ssz + (t + 1)) * Dsz + k;
            xs[b * XS_STR + k] = x[o];
            xs[b * XS_STR + Dsz + k] = mask[o];
        }
        bar_wait(gbase, base + cnt);      // peers' h_new ready
    }
}

static const int SMEM_BYTES =
    (NB * XS_STR + NB * Hsz + NB * 8 * SC_STR +
     2 * NB * NROWB + 2 * NROWB + 8) * (int)sizeof(float);

extern "C" void kernel_launch(void* const* d_in, const int* in_sizes, int n_in,
                              void* d_out, int out_size) {
    const float* x    = (const float*)d_in[0];
    const float* mask = (const float*)d_in[1];
    const float* Wih  = (const float*)d_in[2];
    const float* Whh  = (const float*)d_in[3];
    const float* bih  = (const float*)d_in[4];
    const float* bhh  = (const float*)d_in[5];
    const float* Wro  = (const float*)d_in[6];
    const float* bro  = (const float*)d_in[7];
    float* out = (float*)d_out;

    cudaFuncSetAttribute(rnn_imputer_kernel,
                         cudaFuncAttributeMaxDynamicSharedMemorySize, SMEM_BYTES);
    rnn_imputer_kernel<<<GRID, THREADS, SMEM_BYTES>>>(x, mask, Wih, Whh, bih, bhh,
                                                      Wro, bro, out);
}

// round 5
// speedup vs baseline: 1.5375x; 1.5375x over previous
#include <cuda_runtime.h>
#include <math.h>

// Problem constants
#define Bsz    64
#define Ssz    512
#define Hsz    256
#define Dsz    207
#define DINsz  414

// Partition: 4 batch-groups x 32 hidden-groups = 128 blocks
#define GRID    128
#define THREADS 256
#define NB      16        // batch per block
#define NI      8         // hidden units per block
#define NROWB   24        // 3*NI gate rows
#define XS_STR  420       // 414 padded; pair-broadcast friendly
#define HS_STR  260       // 256 padded
#define HN_STR  9         // h_new scratch stride (conflict-free b*9+j)

// Persistent global state (device globals: no runtime allocation)
__device__ float    g_h[2][Bsz * Hsz];     // double-buffered hidden state
__device__ float    g_xh[3][Bsz * Dsz];    // triple-buffered x_hat accumulators
__device__ unsigned g_flags[GRID * 8];     // one flag per block, 32B apart

// Split-phase group barrier (32-block batch-group scope).
__device__ __forceinline__ void bar_release(unsigned target) {
    __syncthreads();
    if (threadIdx.x == 0) {
        asm volatile("st.release.gpu.u32 [%0], %1;"
                     :: "l"(g_flags + blockIdx.x * 8), "r"(target) : "memory");
    }
}
__device__ __forceinline__ void bar_wait(int gbase, unsigned target) {
    if (threadIdx.x < 32) {
        const unsigned* p = g_flags + (gbase + threadIdx.x) * 8;
        unsigned v;
        do {
            asm volatile("ld.acquire.gpu.u32 %0, [%1];" : "=r"(v) : "l"(p) : "memory");
        } while ((int)(v - target) < 0);
    }
    __syncthreads();
}

__device__ __forceinline__ void fma4(float& a, const float4 wgt, const float4 xv) {
    a = fmaf(wgt.x, xv.x, a);
    a = fmaf(wgt.y, xv.y, a);
    a = fmaf(wgt.z, xv.z, a);
    a = fmaf(wgt.w, xv.w, a);
}

__global__ void __launch_bounds__(THREADS, 1)
rnn_imputer_kernel(const float* __restrict__ x, const float* __restrict__ mask,
                   const float* __restrict__ Wih, const float* __restrict__ Whh,
                   const float* __restrict__ bih, const float* __restrict__ bhh,
                   const float* __restrict__ Wro, const float* __restrict__ bro,
                   float* __restrict__ out)
{
    extern __shared__ float sm[];
    float* wih_s = sm;                        // 24*420
    float* whh_s = wih_s + NROWB * XS_STR;    // 24*260
    float* wro_s = whh_s + NROWB * HS_STR;    // 8*208  (transposed: [j][d])
    float* xs    = wro_s + 8 * 208;           // 16*420  [x_p | mask]
    float* hs    = xs + NB * XS_STR;          // 16*260
    float* hn_s  = hs + NB * HS_STR;          // 16*9   h_new scratch
    float* gi_s  = hn_s + NB * HN_STR;        // 16*24
    float* gh_s  = gi_s + NB * NROWB;         // 16*24
    float* bih_s = gh_s + NB * NROWB;         // 24
    float* bhh_s = bih_s + NROWB;             // 24
    float* bro_s = bhh_s + NROWB;             // 8 (own d-slice)

    const int tid = threadIdx.x, blk = blockIdx.x;
    const int bg = blk >> 5, ig = blk & 31;
    const int gbase = bg << 5;
    const int b0 = bg * NB;
    const int i0 = ig * NI;
    const int d0 = ig * 6 + (ig < 15 ? ig : 15);
    const int nd = (ig < 15) ? 7 : 6;

    const int lane = tid & 31, warp = tid >> 5;
    const int lb = lane & 15, kh = lane >> 4;

    // ---- one-time staging ----
    for (int idx = tid; idx < NROWB * DINsz; idx += THREADS) {
        int r = idx / DINsz, k = idx - r * DINsz;
        int ii = r / 3, g = r - ii * 3;
        wih_s[r * XS_STR + k] = Wih[(g * Hsz + i0 + ii) * DINsz + k];
    }
    for (int idx = tid; idx < NROWB * (XS_STR - DINsz); idx += THREADS) {
        int r = idx / 6, c = idx - r * 6;
        wih_s[r * XS_STR + DINsz + c] = 0.f;
    }
    for (int idx = tid; idx < NROWB * Hsz; idx += THREADS) {
        int r = idx >> 8, k = idx & 255;
        int ii = r / 3, g = r - ii * 3;
        whh_s[r * HS_STR + k] = Whh[(g * Hsz + i0 + ii) * Hsz + k];
    }
    for (int idx = tid; idx < Dsz * 8; idx += THREADS) {
        int d = idx >> 3, j = idx & 7;
        wro_s[j * 208 + d] = Wro[d * Hsz + i0 + j];
    }
    if (tid < NROWB) {
        int ii = tid / 3, g = tid - ii * 3;
        bih_s[tid] = bih[g * Hsz + i0 + ii];
        bhh_s[tid] = bhh[g * Hsz + i0 + ii];
    }
    if (tid < nd) bro_s[tid] = bro[d0 + tid];
    if (tid < NB * 2)  // zero xs[b][414..415]
        xs[(tid >> 1) * XS_STR + DINsz + (tid & 1)] = 0.f;

    // prefetch x[0], mask[0]
    for (int idx = tid; idx < NB * Dsz; idx += THREADS) {
        int b = idx / Dsz, k = idx - b * Dsz;
        size_t o = ((size_t)(b0 + b) * Ssz) * Dsz + k;
        xs[b * XS_STR + k] = x[o];
        xs[b * XS_STR + Dsz + k] = mask[o];
    }

    // init state: h0 = 0 (buffer 0); x_hat buffers 0,1 = bias (own tile)
    if (tid < NB * NI) {
        int b = tid >> 3, ii = tid & 7;
        g_h[0][(b0 + b) * Hsz + i0 + ii] = 0.f;
    }
    if (tid < nd * NB) {
        int dd = tid >> 4, b = tid & 15;
        float bv = bro[d0 + dd];
        g_xh[0][(b0 + b) * Dsz + d0 + dd] = bv;
        g_xh[1][(b0 + b) * Dsz + d0 + dd] = bv;
    }

    unsigned base = *(volatile unsigned*)(g_flags + blk * 8);
    unsigned cnt = 0;
    bar_release(base + (++cnt));
    bar_wait(gbase, base + cnt);     // init complete

    for (int t = 0; t < Ssz; ++t) {
        const float* xh_cur = g_xh[t % 3];
        float* xh_nxt = g_xh[(t + 1) % 3];
        float* xh_zer = g_xh[(t + 2) % 3];

        // ---- store out[:, t, own d-slice] from completed x_hat_t ----
        if (tid < nd * NB) {
            int dd = tid >> 4, b = tid & 15;
            int gb = b0 + b;
            out[((size_t)gb * Ssz + t) * Dsz + d0 + dd] =
                __ldcg(xh_cur + gb * Dsz + d0 + dd);
        }
        if (t == Ssz - 1) break;

        // ---- stage h_t ----
        const float* hsrc = g_h[t & 1];
        for (int idx = tid; idx < NB * 64; idx += THREADS) {
            int b = idx >> 6, c = idx & 63;
            float4 v = __ldcg(reinterpret_cast<const float4*>(hsrc + (b0 + b) * Hsz) + c);
            *(reinterpret_cast<float4*>(hs + b * HS_STR) + c) = v;
        }
        // ---- patch unobserved entries with x_hat_t ----
        for (int idx = tid; idx < NB * Dsz; idx += THREADS) {
            int b = idx / Dsz, k = idx - b * Dsz;
            float mv = xs[b * XS_STR + Dsz + k];
            if (mv <= 0.5f)
                xs[b * XS_STR + k] = __ldcg(xh_cur + (b0 + b) * Dsz + k);
        }
        __syncthreads();

        // ---- gh = Whh_slice @ h (3 rows per warp) ----
        {
            const int r0 = warp * 3;
            float a0 = 0.f, a1 = 0.f, a2 = 0.f;
            const float4* xp = reinterpret_cast<const float4*>(hs + lb * HS_STR) + kh;
            const float4* w0 = reinterpret_cast<const float4*>(whh_s + r0 * HS_STR) + kh;
            const float4* w1 = reinterpret_cast<const float4*>(whh_s + (r0 + 1) * HS_STR) + kh;
            const float4* w2 = reinterpret_cast<const float4*>(whh_s + (r0 + 2) * HS_STR) + kh;
#pragma unroll 8
            for (int kk = 0; kk < 32; ++kk) {
                float4 xv = xp[2 * kk];
                fma4(a0, w0[2 * kk], xv);
                fma4(a1, w1[2 * kk], xv);
                fma4(a2, w2[2 * kk], xv);
            }
            a0 += __shfl_xor_sync(0xffffffffu, a0, 16);
            a1 += __shfl_xor_sync(0xffffffffu, a1, 16);
            a2 += __shfl_xor_sync(0xffffffffu, a2, 16);
            if (lane < 16) {
                gh_s[lb * NROWB + r0]     = a0;
                gh_s[lb * NROWB + r0 + 1] = a1;
                gh_s[lb * NROWB + r0 + 2] = a2;
            }
        }
        // ---- gi = Wih_slice @ x_in (3 rows per warp) ----
        {
            const int r0 = warp * 3;
            float a0 = 0.f, a1 = 0.f, a2 = 0.f;
            const float4* xp = reinterpret_cast<const float4*>(xs + lb * XS_STR) + kh;
            const float4* w0 = reinterpret_cast<const float4*>(wih_s + r0 * XS_STR) + kh;
            const float4* w1 = reinterpret_cast<const float4*>(wih_s + (r0 + 1) * XS_STR) + kh;
            const float4* w2 = reinterpret_cast<const float4*>(wih_s + (r0 + 2) * XS_STR) + kh;
#pragma unroll 4
            for (int kk = 0; kk < 52; ++kk) {
                float4 xv = xp[2 * kk];
                fma4(a0, w0[2 * kk], xv);
                fma4(a1, w1[2 * kk], xv);
                fma4(a2, w2[2 * kk], xv);
            }
            a0 += __shfl_xor_sync(0xffffffffu, a0, 16);
            a1 += __shfl_xor_sync(0xffffffffu, a1, 16);
            a2 += __shfl_xor_sync(0xffffffffu, a2, 16);
            if (lane < 16) {
                gi_s[lb * NROWB + r0]     = a0;
                gi_s[lb * NROWB + r0 + 1] = a1;
                gi_s[lb * NROWB + r0 + 2] = a2;
            }
        }
        __syncthreads();

        // ---- gates -> h_new (slice); re-init zero buffer with bias ----
        if (tid < NB * NI) {
            int b = tid >> 3, ii = tid & 7;
            int r3 = ii * 3;
            float ir  = gi_s[b * NROWB + r3]     + bih_s[r3];
            float iz  = gi_s[b * NROWB + r3 + 1] + bih_s[r3 + 1];
            float inn = gi_s[b * NROWB + r3 + 2] + bih_s[r3 + 2];
            float hr  = gh_s[b * NROWB + r3]     + bhh_s[r3];
            float hz  = gh_s[b * NROWB + r3 + 1] + bhh_s[r3 + 1];
            float hn  = gh_s[b * NROWB + r3 + 2] + bhh_s[r3 + 2];
            float r = 1.f / (1.f + expf(-(ir + hr)));
            float z = 1.f / (1.f + expf(-(iz + hz)));
            float n = tanhf(inn + r * hn);
            float hold = hs[b * HS_STR + i0 + ii];
            float hv = (1.f - z) * n + z * hold;
            hn_s[b * HN_STR + ii] = hv;
            g_h[(t + 1) & 1][(b0 + b) * Hsz + i0 + ii] = hv;
        } else if (tid >= 128 && tid - 128 < nd * NB) {
            int e = tid - 128;
            int dd = e >> 4, b = e & 15;
            xh_zer[(b0 + b) * Dsz + d0 + dd] = bro_s[dd];
        }
        __syncthreads();

        // ---- rank-8 partial readout: RED into x_hat_{t+1} ----
        for (int e = tid; e < Dsz * NB; e += THREADS) {
            int d = e >> 4, b = e & 15;
            float a = 0.f;
#pragma unroll
            for (int j = 0; j < 8; ++j)
                a = fmaf(wro_s[j * 208 + d], hn_s[b * HN_STR + j], a);
            atomicAdd(xh_nxt + (b0 + b) * Dsz + d, a);
        }

        bar_release(base + (++cnt));

        // ---- prefetch x[t+1] (overlaps barrier) ----
        for (int idx = tid; idx < NB * Dsz; idx += THREADS) {
            int b = idx / Dsz, k = idx - b * Dsz;
            size_t o = ((size_t)(b0 + b) * Ssz + (t + 1)) * Dsz + k;
            xs[b * XS_STR + k] = x[o];
            xs[b * XS_STR + Dsz + k] = mask[o];
        }
        bar_wait(gbase, base + cnt);
    }
}

static const int SMEM_BYTES =
    (NROWB * XS_STR + NROWB * HS_STR + 8 * 208 + NB * XS_STR + NB * HS_STR +
     NB * HN_STR + 2 * NB * NROWB + 2 * NROWB + 8) * (int)sizeof(float);

extern "C" void kernel_launch(void* const* d_in, const int* in_sizes, int n_in,
                              void* d_out, int out_size) {
    const float* x    = (const float*)d_in[0];
    const float* mask = (const float*)d_in[1];
    const float* Wih  = (const float*)d_in[2];
    const float* Whh  = (const float*)d_in[3];
    const float* bih  = (const float*)d_in[4];
    const float* bhh  = (const float*)d_in[5];
    const float* Wro  = (const float*)d_in[6];
    const float* bro  = (const float*)d_in[7];
    float* out = (float*)d_out;

    cudaFuncSetAttribute(rnn_imputer_kernel,
                         cudaFuncAttributeMaxDynamicSharedMemorySize, SMEM_BYTES);
    rnn_imputer_kernel<<<GRID, THREADS, SMEM_BYTES>>>(x, mask, Wih, Whh, bih, bhh,
                                                      Wro, bro, out);
}

// round 7
// speedup vs baseline: 1.7323x; 1.1267x over previous
#include <cuda_runtime.h>
#include <math.h>

// Problem constants
#define Bsz    64
#define Ssz    512
#define Hsz    256
#define Dsz    207
#define DINsz  414

// Partition: 4 batch-groups x 32 hidden-groups = 128 blocks
#define GRID    128
#define THREADS 512
#define NB      16        // batch per block
#define NI      8         // hidden units per block
#define NROWB   24        // 3*NI gate rows
#define XS_STR  420       // 414 padded (float4-aligned)
#define HS_STR  260       // 256 padded

// Persistent global state (device globals: no runtime allocation)
__device__ float    g_h[Bsz * Hsz];
__device__ float    g_xh[Bsz * Dsz];
__device__ unsigned g_flags[GRID * 8];   // one flag per block, 32B apart

// Split-phase group barrier (32-block batch-group scope).
__device__ __forceinline__ void bar_release(unsigned target) {
    __syncthreads();
    if (threadIdx.x == 0) {
        asm volatile("st.release.gpu.u32 [%0], %1;"
                     :: "l"(g_flags + blockIdx.x * 8), "r"(target) : "memory");
    }
}
__device__ __forceinline__ void bar_wait(int gbase, unsigned target) {
    if (threadIdx.x < 32) {
        const unsigned* p = g_flags + (gbase + threadIdx.x) * 8;
        unsigned v;
        do {
            asm volatile("ld.acquire.gpu.u32 %0, [%1];" : "=r"(v) : "l"(p) : "memory");
        } while ((int)(v - target) < 0);
    }
    __syncthreads();
}

__device__ __forceinline__ void fma4(float& a, const float4 wgt, const float4 xv) {
    a = fmaf(wgt.x, xv.x, a);
    a = fmaf(wgt.y, xv.y, a);
    a = fmaf(wgt.z, xv.z, a);
    a = fmaf(wgt.w, xv.w, a);
}

__global__ void __launch_bounds__(THREADS, 1)
rnn_imputer_kernel(const float* __restrict__ x, const float* __restrict__ mask,
                   const float* __restrict__ Wih, const float* __restrict__ Whh,
                   const float* __restrict__ bih, const float* __restrict__ bhh,
                   const float* __restrict__ Wro, const float* __restrict__ bro,
                   float* __restrict__ out)
{
    extern __shared__ float sm[];
    float* wih_s = sm;                        // 24*420
    float* wa_s  = wih_s + NROWB * XS_STR;    // 31*260  (Whh rows 0..23, Wro rows 24..)
    float* xs    = wa_s + 31 * HS_STR;        // 16*420  [x_p | mask]
    float* hs    = xs + NB * XS_STR;          // 16*260
    float* gi_s  = hs + NB * HS_STR;          // 16*24
    float* gh_s  = gi_s + NB * NROWB;         // 16*24
    float* bih_s = gh_s + NB * NROWB;         // 24
    float* bhh_s = bih_s + NROWB;             // 24
    float* bro_s = bhh_s + NROWB;             // 8

    const int tid = threadIdx.x, blk = blockIdx.x;
    const int bg = blk >> 5, ig = blk & 31;
    const int gbase = bg << 5;
    const int b0 = bg * NB;
    const int i0 = ig * NI;
    const int d0 = ig * 6 + (ig < 15 ? ig : 15);
    const int nd = (ig < 15) ? 7 : 6;

    const int lane = tid & 31, warp = tid >> 5;
    const int rw = warp & 7;                 // row-group within warp-half
    const int bh = (warp >> 3) * 8;          // batch-half base (0 or 8)
    const int lb = lane & 7;                 // batch within half
    const int kq = lane >> 3;                // K quarter (0..3)
    const int b = bh + lb;                   // this lane's batch (0..15)

    // ---- one-time staging ----
    for (int idx = tid; idx < NROWB * DINsz; idx += THREADS) {
        int r = idx / DINsz, k = idx - r * DINsz;
        int ii = r / 3, g = r - ii * 3;
        wih_s[r * XS_STR + k] = Wih[(g * Hsz + i0 + ii) * DINsz + k];
    }
    for (int idx = tid; idx < NROWB * (XS_STR - DINsz); idx += THREADS) {
        int r = idx / 6, c = idx - r * 6;
        wih_s[r * XS_STR + DINsz + c] = 0.f;
    }
    for (int idx = tid; idx < NROWB * Hsz; idx += THREADS) {
        int r = idx >> 8, k = idx & 255;
        int ii = r / 3, g = r - ii * 3;
        wa_s[r * HS_STR + k] = Whh[(g * Hsz + i0 + ii) * Hsz + k];
    }
    for (int idx = tid; idx < nd * Hsz; idx += THREADS) {
        int r = idx >> 8, k = idx & 255;
        wa_s[(NROWB + r) * HS_STR + k] = Wro[(d0 + r) * Hsz + k];
    }
    if (tid < NB * 2)  // zero xs[b][414..415]
        xs[(tid >> 1) * XS_STR + DINsz + (tid & 1)] = 0.f;
    if (tid < NROWB) {
        int ii = tid / 3, g = tid - ii * 3;
        bih_s[tid] = bih[g * Hsz + i0 + ii];
        bhh_s[tid] = bhh[g * Hsz + i0 + ii];
    }
    if (tid < nd) bro_s[tid] = bro[d0 + tid];

    // prefetch x[0], mask[0]
    for (int idx = tid; idx < NB * Dsz; idx += THREADS) {
        int bb = idx / Dsz, k = idx - bb * Dsz;
        size_t o = ((size_t)(b0 + bb) * Ssz) * Dsz + k;
        xs[bb * XS_STR + k] = x[o];
        xs[bb * XS_STR + Dsz + k] = mask[o];
    }
    // zero my slice of h state
    if (tid < NB * NI) {
        int bb = tid >> 3, ii = tid & 7;
        g_h[(b0 + bb) * Hsz + i0 + ii] = 0.f;
    }

    unsigned base = *(volatile unsigned*)(g_flags + blk * 8);
    unsigned cnt = 0;
    bar_release(base + (++cnt));
    bar_wait(gbase, base + cnt);     // init complete

    for (int t = 0; t < Ssz; ++t) {
        // ---- stage h_t ----
        for (int idx = tid; idx < NB * 64; idx += THREADS) {
            int bb = idx >> 6, c = idx & 63;
            float4 v = __ldcg(reinterpret_cast<const float4*>(g_h + (b0 + bb) * Hsz) + c);
            *(reinterpret_cast<float4*>(hs + bb * HS_STR) + c) = v;
        }
        __syncthreads();

        // ---- A1: readout rows FIRST (x_hat needed by peers) ----
        if (rw < nd) {
            const int row = NROWB + rw;
            float a = 0.f;
            const float4* xp = reinterpret_cast<const float4*>(hs + b * HS_STR + kq * 64);
            const float4* wp = reinterpret_cast<const float4*>(wa_s + row * HS_STR + kq * 64);
#pragma unroll
            for (int kk = 0; kk < 16; ++kk) fma4(a, wp[kk], xp[kk]);
            a += __shfl_xor_sync(0xffffffffu, a, 8);
            a += __shfl_xor_sync(0xffffffffu, a, 16);
            if (lane < 8) {
                int gb = b0 + b;
                float v = a + bro_s[rw];
                g_xh[gb * Dsz + d0 + rw] = v;
                out[((size_t)gb * Ssz + t) * Dsz + d0 + rw] = v;
            }
        }
        if (t == Ssz - 1) break;          // last step: only readout needed
        bar_release(base + (++cnt));      // publish x_hat (syncthreads inside)

        // ---- A2: gh = Whh_slice @ h (3 rows per warp, overlaps barrier A) ----
        {
            const int r0 = rw * 3;
            float a0 = 0.f, a1 = 0.f, a2 = 0.f;
            const float4* xp = reinterpret_cast<const float4*>(hs + b * HS_STR + kq * 64);
            const float4* w0 = reinterpret_cast<const float4*>(wa_s + r0 * HS_STR + kq * 64);
            const float4* w1 = reinterpret_cast<const float4*>(wa_s + (r0 + 1) * HS_STR + kq * 64);
            const float4* w2 = reinterpret_cast<const float4*>(wa_s + (r0 + 2) * HS_STR + kq * 64);
#pragma unroll
            for (int kk = 0; kk < 16; ++kk) {
                float4 xv = xp[kk];
                fma4(a0, w0[kk], xv);
                fma4(a1, w1[kk], xv);
                fma4(a2, w2[kk], xv);
            }
            a0 += __shfl_xor_sync(0xffffffffu, a0, 8);
            a0 += __shfl_xor_sync(0xffffffffu, a0, 16);
            a1 += __shfl_xor_sync(0xffffffffu, a1, 8);
            a1 += __shfl_xor_sync(0xffffffffu, a1, 16);
            a2 += __shfl_xor_sync(0xffffffffu, a2, 8);
            a2 += __shfl_xor_sync(0xffffffffu, a2, 16);
            if (lane < 8) {
                gh_s[b * NROWB + r0]     = a0;
                gh_s[b * NROWB + r0 + 1] = a1;
                gh_s[b * NROWB + r0 + 2] = a2;
            }
        }
        bar_wait(gbase, base + cnt);      // peers' x_hat ready

        // ---- B0: patch unobserved entries with x_hat ----
        for (int idx = tid; idx < NB * Dsz; idx += THREADS) {
            int bb = idx / Dsz, k = idx - bb * Dsz;
            float mv = xs[bb * XS_STR + Dsz + k];
            if (mv <= 0.5f)
                xs[bb * XS_STR + k] = __ldcg(g_xh + (b0 + bb) * Dsz + k);
        }
        __syncthreads();

        // ---- B1: gi = Wih_slice @ x_in (3 rows per warp, K quarters of 104) ----
        {
            const int r0 = rw * 3;
            float a0 = 0.f, a1 = 0.f, a2 = 0.f;
            const float4* xp = reinterpret_cast<const float4*>(xs + b * XS_STR + kq * 104);
            const float4* w0 = reinterpret_cast<const float4*>(wih_s + r0 * XS_STR + kq * 104);
            const float4* w1 = reinterpret_cast<const float4*>(wih_s + (r0 + 1) * XS_STR + kq * 104);
            const float4* w2 = reinterpret_cast<const float4*>(wih_s + (r0 + 2) * XS_STR + kq * 104);
#pragma unroll
            for (int kk = 0; kk < 26; ++kk) {
                float4 xv = xp[kk];
                fma4(a0, w0[kk], xv);
                fma4(a1, w1[kk], xv);
                fma4(a2, w2[kk], xv);
            }
            a0 += __shfl_xor_sync(0xffffffffu, a0, 8);
            a0 += __shfl_xor_sync(0xffffffffu, a0, 16);
            a1 += __shfl_xor_sync(0xffffffffu, a1, 8);
            a1 += __shfl_xor_sync(0xffffffffu, a1, 16);
            a2 += __shfl_xor_sync(0xffffffffu, a2, 8);
            a2 += __shfl_xor_sync(0xffffffffu, a2, 16);
            if (lane < 8) {
                gi_s[b * NROWB + r0]     = a0;
                gi_s[b * NROWB + r0 + 1] = a1;
                gi_s[b * NROWB + r0 + 2] = a2;
            }
        }
        __syncthreads();

        // ---- B2: gates -> h_new ----
        if (tid < NB * NI) {
            int bb = tid >> 3, ii = tid & 7;
            int r3 = ii * 3;
            float ir  = gi_s[bb * NROWB + r3]     + bih_s[r3];
            float iz  = gi_s[bb * NROWB + r3 + 1] + bih_s[r3 + 1];
            float inn = gi_s[bb * NROWB + r3 + 2] + bih_s[r3 + 2];
            float hr  = gh_s[bb * NROWB + r3]     + bhh_s[r3];
            float hz  = gh_s[bb * NROWB + r3 + 1] + bhh_s[r3 + 1];
            float hn  = gh_s[bb * NROWB + r3 + 2] + bhh_s[r3 + 2];
            float r = 1.f / (1.f + expf(-(ir + hr)));
            float z = 1.f / (1.f + expf(-(iz + hz)));
            float n = tanhf(inn + r * hn);
            float hold = hs[bb * HS_STR + i0 + ii];
            g_h[(b0 + bb) * Hsz + i0 + ii] = (1.f - z) * n + z * hold;
        }
        bar_release(base + (++cnt));      // publish h_new (syncthreads inside)

        // ---- prefetch x[t+1], mask[t+1] (overlaps barrier B) ----
        for (int idx = tid; idx < NB * Dsz; idx += THREADS) {
            int bb = idx / Dsz, k = idx - bb * Dsz;
            size_t o = ((size_t)(b0 + bb) * Ssz + (t + 1)) * Dsz + k;
            xs[bb * XS_STR + k] = x[o];
            xs[bb * XS_STR + Dsz + k] = mask[o];
        }
        bar_wait(gbase, base + cnt);      // peers' h_new ready
    }
}

static const int SMEM_BYTES =
    (NROWB * XS_STR + 31 * HS_STR + NB * XS_STR + NB * HS_STR +
     2 * NB * NROWB + 2 * NROWB + 8) * (int)sizeof(float);

extern "C" void kernel_launch(void* const* d_in, const int* in_sizes, int n_in,
                              void* d_out, int out_size) {
    const float* x    = (const float*)d_in[0];
    const float* mask = (const float*)d_in[1];
    const float* Wih  = (const float*)d_in[2];
    const float* Whh  = (const float*)d_in[3];
    const float* bih  = (const float*)d_in[4];
    const float* bhh  = (const float*)d_in[5];
    const float* Wro  = (const float*)d_in[6];
    const float* bro  = (const float*)d_in[7];
    float* out = (float*)d_out;

    cudaFuncSetAttribute(rnn_imputer_kernel,
                         cudaFuncAttributeMaxDynamicSharedMemorySize, SMEM_BYTES);
    rnn_imputer_kernel<<<GRID, THREADS, SMEM_BYTES>>>(x, mask, Wih, Whh, bih, bhh,
                                                      Wro, bro, out);
}